// round 7
// baseline (speedup 1.0000x reference)
#include <cuda_runtime.h>
#include <cuda.h>
#include <cstdint>

// ---------------- constants ----------------
#define TT    9
#define BB    8
#define CC    256
#define HWHW  3136
#define PIX   16
#define NTHREADS 1024
#define TILES_PER_B 196          // 3136/16
#define GRID  148                // persistent, 1 CTA/SM

#define CH_T      3                      // t-slices per chunk
#define CH_FLOATS (CH_T*CC*PIX)          // 12288 floats = 49152 B
#define CH_BYTES  (CH_FLOATS*4)
#define NRING     4

// SMEM layout (float offsets)
#define OFF_RING 0                           // [4][CH_FLOATS]
#define OFF_PART (NRING*CH_FLOATS)           // 49152  [32 warps][160]
#define OFF_SCOR (OFF_PART + 32*160)         // 54272  [160]
#define OFF_MBAR (OFF_SCOR + 160)            // 54432  (4 x u64; byte 217728, 8B aligned)
#define SMEM_FLOATS (OFF_MBAR + 8)
#define SMEM_BYTES  (SMEM_FLOATS * 4)        // 217760 B

// ---------------- PTX helpers ----------------
#define MBAR_INIT(addr, cnt) \
    asm volatile("mbarrier.init.shared.b64 [%0], %1;" :: "r"(addr), "r"(cnt) : "memory")
#define MBAR_EXPECT_TX(addr, bytes) \
    asm volatile("mbarrier.arrive.expect_tx.shared.b64 _, [%0], %1;" :: "r"(addr), "r"(bytes) : "memory")
#define MBAR_WAIT(addr, parity) do {                                           \
    asm volatile("{\n\t.reg .pred P;\n\t"                                      \
        "WL_%=:\n\t"                                                           \
        "mbarrier.try_wait.parity.acquire.cta.shared::cta.b64 P, [%0], %1, 0x989680;\n\t" \
        "@P bra WD_%=;\n\t"                                                    \
        "bra WL_%=;\n\t"                                                       \
        "WD_%=:\n\t}"                                                          \
        :: "r"(addr), "r"(parity) : "memory");                                 \
} while (0)

__device__ __forceinline__ void tma_load4d(uint32_t dst, const CUtensorMap* map,
                                           int x, int z, int tw, uint32_t mbar)
{
    asm volatile(
        "cp.async.bulk.tensor.4d.shared::cta.global.tile.mbarrier::complete_tx::bytes "
        "[%0], [%1, {%2, %3, %4, %5}], [%6];"
        :: "r"(dst), "l"(map), "r"(x), "r"(0), "r"(z), "r"(tw), "r"(mbar)
        : "memory");
}

// issue global chunk ci (relative to this block's range start g0)
__device__ __forceinline__ void issue_chunk(uint32_t smem_base, uint32_t mbar_base,
                                            const CUtensorMap* map, int g0, int ci)
{
    const int g    = g0 + ci / 3;
    const int j    = ci % 3;
    const int bidx = g / TILES_PER_B;
    const int pix0 = (g % TILES_PER_B) * PIX;
    const int slot = ci & (NRING - 1);
    const uint32_t mb  = mbar_base + slot * 8;
    const uint32_t dst = smem_base + (uint32_t)(slot * CH_BYTES);
    MBAR_EXPECT_TX(mb, CH_BYTES);
    tma_load4d(dst, map, pix0, bidx, j * CH_T, mb);
}

// ---------------- main kernel ----------------
__global__ __launch_bounds__(NTHREADS, 1)
void tfma_ring_kernel(const __grid_constant__ CUtensorMap tmap,   // box {16,256,1,3}
                      const float* __restrict__ wptr,
                      const float* __restrict__ bptr,
                      const float* __restrict__ gptr,
                      float* __restrict__ out)
{
    extern __shared__ float sm[];
    float* part = sm + OFF_PART;
    float* scor = sm + OFF_SCOR;
    const uint32_t smem_base = (uint32_t)__cvta_generic_to_shared(sm);
    const uint32_t mbar_base = smem_base + OFF_MBAR * 4;

    const int tid  = threadIdx.x;
    const int lane = tid & 31;
    const int wrp  = tid >> 5;
    const int p    = tid & (PIX - 1);   // 0..15
    const int cg   = tid >> 4;          // 0..63

    // static balanced tile range over 1568 tiles
    const int g0  = (int)(((long)blockIdx.x * 392) / 37);
    const int g1  = (int)(((long)(blockIdx.x + 1) * 392) / 37);
    const int cnt = g1 - g0;
    if (cnt <= 0) return;
    const int nchunks = 3 * cnt;

    // preload weights to registers
    float wct[4], wot[4];
    #pragma unroll
    for (int ci = 0; ci < 4; ++ci) {
        wct[ci] = wptr[cg + (ci << 6)];
        wot[ci] = wptr[CC + cg + (ci << 6)];
    }
    const float bv    = bptr[0];
    const float gamma = gptr[0];

    if (tid == 0) {
        #pragma unroll
        for (int s = 0; s < NRING; ++s)
            MBAR_INIT(mbar_base + s * 8, 1);
    }
    __syncthreads();

    // prologue: fill the ring
    if (tid == 0) {
        #pragma unroll
        for (int i = 0; i < NRING; ++i)
            if (i < nchunks) issue_chunk(smem_base, mbar_base, &tmap, g0, i);
    }

    #pragma unroll 1
    for (int k = 0; k < cnt; ++k) {
        const int g    = g0 + k;
        const int bidx = g / TILES_PER_B;
        const int pix0 = (g % TILES_PER_B) * PIX;
        const int k3   = 3 * k;

        float rv[4][TT];
        float acc[TT];
        float accc = 0.f;
        #pragma unroll
        for (int t = 0; t < TT; ++t) acc[t] = 0.f;

        // ---- consume the tile's 3 chunks ----
        #pragma unroll
        for (int j = 0; j < 3; ++j) {
            const int i    = k3 + j;
            const int slot = i & (NRING - 1);
            const int ph   = (i >> 2) & 1;
            MBAR_WAIT(mbar_base + slot * 8, ph);

            const float* buf = sm + slot * CH_FLOATS;
            #pragma unroll
            for (int ci = 0; ci < 4; ++ci) {
                const int c = cg + (ci << 6);
                #pragma unroll
                for (int tl = 0; tl < CH_T; ++tl) {
                    const int t = j * CH_T + tl;
                    rv[ci][t] = buf[(tl * CC + c) * PIX + p];
                    acc[t] = fmaf(rv[ci][t], wot[ci], acc[t]);
                    if (t == TT / 2) accc = fmaf(rv[ci][t], wct[ci], accc);
                }
            }

            if (j == 2) {
                // warp partials: xor16 combines the warp's two c-groups
                #pragma unroll
                for (int t = 0; t < TT; ++t)
                    acc[t] += __shfl_xor_sync(0xffffffffu, acc[t], 16);
                accc += __shfl_xor_sync(0xffffffffu, accc, 16);
                if (lane < PIX) {
                    #pragma unroll
                    for (int t = 0; t < TT; ++t)
                        part[wrp * 160 + t * PIX + lane] = acc[t];
                    part[wrp * 160 + TT * PIX + lane] = accc;
                }
            }
            __syncthreads();              // chunk consumed (+ partials if j==2)

            // refill this slot with chunk i+4
            if (tid == 0 && i + NRING < nchunks)
                issue_chunk(smem_base, mbar_base, &tmap, g0, i + NRING);
        }

        // ---- cross-warp reduce: 160 threads ----
        if (tid < 160) {
            float s = 0.f;
            #pragma unroll
            for (int w = 0; w < 32; ++w) s += part[w * 160 + tid];
            scor[tid] = s;
        }
        __syncthreads();

        // ---- softmax + attended sum + residual (from registers) ----
        {
            const float centv = scor[TT * PIX + p];
            float a[TT];
            float m = -1e30f;
            #pragma unroll
            for (int t = 0; t < TT; ++t) {
                a[t] = scor[t * PIX + p] + centv + bv;
                m = fmaxf(m, a[t]);
            }
            float sum = 0.f;
            #pragma unroll
            for (int t = 0; t < TT; ++t) {
                a[t] = __expf(a[t] - m);
                sum += a[t];
            }
            const float inv = 1.f / sum;
            #pragma unroll
            for (int t = 0; t < TT; ++t) a[t] *= inv;

            float* ob = out + (size_t)bidx * CC * HWHW + pix0 + p;
            #pragma unroll
            for (int ci = 0; ci < 4; ++ci) {
                const int c = cg + (ci << 6);
                float s = 0.f;
                #pragma unroll
                for (int t = 0; t < TT; ++t)
                    s = fmaf(a[t], rv[ci][t], s);
                ob[(size_t)c * HWHW] = rv[ci][TT / 2] + gamma * s;
            }
        }
        // scor/part reuse protected by the chunk barriers of the next tile
        // (next partials write happens after 3 more barriers).
    }
}

// ---------------- fallback kernel (proven cp.async path) ----------------
#define FBPIX 8
#define FB_NT 7
#define FB_CHUNKS 56
#define FB_TILEF (TT*CC*FBPIX)
#define FB_OFF_WC   (2*FB_TILEF)
#define FB_OFF_WO   (FB_OFF_WC + CC)
#define FB_OFF_PART (FB_OFF_WO + CC)
#define FB_OFF_SCOR (FB_OFF_PART + 16*80)
#define FB_SMEM_BYTES ((FB_OFF_SCOR + 80) * 4)

__device__ __forceinline__ void fb_issue_tile(uint32_t smem_dst_bytes,
                                              const float* __restrict__ src, int tid)
{
    const int q = tid & 1;
    const int c = tid >> 1;
    const float* g = src + (size_t)c * HWHW + q * 4;
    uint32_t s = smem_dst_bytes + (uint32_t)((c * FBPIX + q * 4) * 4);
    #pragma unroll
    for (int t = 0; t < TT; ++t) {
        asm volatile("cp.async.cg.shared.global [%0], [%1], 16;\n"
                     :: "r"(s), "l"(g) : "memory");
        g += (size_t)BB * CC * HWHW;
        s += CC * FBPIX * 4;
    }
}

__global__ __launch_bounds__(512, 1)
void tfma_fb_kernel(const float* __restrict__ seq,
                    const float* __restrict__ wptr,
                    const float* __restrict__ bptr,
                    const float* __restrict__ gptr,
                    float* __restrict__ out)
{
    extern __shared__ float sm[];
    float* wc   = sm + FB_OFF_WC;
    float* wo   = sm + FB_OFF_WO;
    float* part = sm + FB_OFF_PART;
    float* scor = sm + FB_OFF_SCOR;
    const uint32_t smem_base = (uint32_t)__cvta_generic_to_shared(sm);

    const int tid  = threadIdx.x;
    const int lane = tid & 31;
    const int wrp  = tid >> 5;
    const int p    = tid & (FBPIX - 1);
    const int cg   = tid >> 3;
    const int bidx  = blockIdx.x / FB_CHUNKS;
    const int chunk = blockIdx.x % FB_CHUNKS;
    const float* tbase = seq + (size_t)bidx * CC * HWHW;

    if (tid < CC) { wc[tid] = wptr[tid]; wo[tid] = wptr[CC + tid]; }

    fb_issue_tile(smem_base, tbase + (size_t)(chunk * FB_NT) * FBPIX, tid);
    asm volatile("cp.async.commit_group;\n" ::: "memory");

    const float bv    = bptr[0];
    const float gamma = gptr[0];
    float* obase0 = out + (size_t)bidx * CC * HWHW;

    for (int k = 0; k < FB_NT; ++k) {
        if (k + 1 < FB_NT)
            fb_issue_tile(smem_base + ((k & 1) ? 0 : FB_TILEF) * 4,
                          tbase + (size_t)((chunk * FB_NT + k + 1) * FBPIX), tid);
        asm volatile("cp.async.commit_group;\n" ::: "memory");
        asm volatile("cp.async.wait_group 1;\n" ::: "memory");
        __syncthreads();

        const float* tile = sm + ((k & 1) ? FB_TILEF : 0);
        const int pix0 = (chunk * FB_NT + k) * FBPIX;

        float rv[4][TT];
        float acc[TT]; float accc = 0.f;
        #pragma unroll
        for (int t = 0; t < TT; ++t) acc[t] = 0.f;
        #pragma unroll
        for (int ci = 0; ci < 4; ++ci) {
            const int c = cg + (ci << 6);
            const float wotv = wo[c], wctv = wc[c];
            #pragma unroll
            for (int t = 0; t < TT; ++t) {
                rv[ci][t] = tile[(t * CC + c) * FBPIX + p];
                acc[t] = fmaf(rv[ci][t], wotv, acc[t]);
                if (t == TT / 2) accc = fmaf(rv[ci][t], wctv, accc);
            }
        }
        #pragma unroll
        for (int t = 0; t < TT; ++t) {
            acc[t] += __shfl_xor_sync(0xffffffffu, acc[t], 8);
            acc[t] += __shfl_xor_sync(0xffffffffu, acc[t], 16);
        }
        accc += __shfl_xor_sync(0xffffffffu, accc, 8);
        accc += __shfl_xor_sync(0xffffffffu, accc, 16);
        if (lane < FBPIX) {
            #pragma unroll
            for (int t = 0; t < TT; ++t) part[wrp * 80 + t * FBPIX + lane] = acc[t];
            part[wrp * 80 + TT * FBPIX + lane] = accc;
        }
        __syncthreads();
        if (tid < 80) {
            float s = 0.f;
            #pragma unroll
            for (int g = 0; g < 16; ++g) s += part[g * 80 + tid];
            scor[tid] = s;
        }
        __syncthreads();
        {
            const float centv = scor[TT * FBPIX + p];
            float a[TT]; float m = -1e30f;
            #pragma unroll
            for (int t = 0; t < TT; ++t) { a[t] = scor[t * FBPIX + p] + centv + bv; m = fmaxf(m, a[t]); }
            float sum = 0.f;
            #pragma unroll
            for (int t = 0; t < TT; ++t) { a[t] = __expf(a[t] - m); sum += a[t]; }
            const float inv = 1.f / sum;
            #pragma unroll
            for (int t = 0; t < TT; ++t) a[t] *= inv;

            float* ob = obase0 + pix0 + p;
            #pragma unroll
            for (int ci = 0; ci < 4; ++ci) {
                const int c = cg + (ci << 6);
                float s = 0.f;
                #pragma unroll
                for (int t = 0; t < TT; ++t) s = fmaf(a[t], rv[ci][t], s);
                ob[(size_t)c * HWHW] = rv[ci][TT / 2] + gamma * s;
            }
        }
        __syncthreads();
    }
}

// ---------------- host ----------------
typedef CUresult (*EncodeTiledFn)(CUtensorMap*, CUtensorMapDataType, cuuint32_t, void*,
                                  const cuuint64_t*, const cuuint64_t*,
                                  const cuuint32_t*, const cuuint32_t*,
                                  CUtensorMapInterleave, CUtensorMapSwizzle,
                                  CUtensorMapL2promotion, CUtensorMapFloatOOBfill);

extern "C" void kernel_launch(void* const* d_in, const int* in_sizes, int n_in,
                              void* d_out, int out_size)
{
    (void)in_sizes; (void)n_in; (void)out_size;
    const float* seq   = (const float*)d_in[0];
    const float* w     = (const float*)d_in[1];
    const float* bv    = (const float*)d_in[2];
    const float* gamma = (const float*)d_in[3];
    float* out = (float*)d_out;

    void* fn = nullptr;
    cudaDriverEntryPointQueryResult qr = cudaDriverEntryPointSymbolNotFound;
    cudaGetDriverEntryPointByVersion("cuTensorMapEncodeTiled", &fn, 12000,
                                     cudaEnableDefault, &qr);

    bool tma_ok = false;
    CUtensorMap tmap;
    if (fn && qr == cudaDriverEntryPointSuccess) {
        cuuint64_t dims[4]    = {HWHW, CC, BB, TT};
        cuuint64_t strides[3] = {(cuuint64_t)HWHW * 4,
                                 (cuuint64_t)CC * HWHW * 4,
                                 (cuuint64_t)BB * CC * HWHW * 4};
        cuuint32_t estr[4]    = {1, 1, 1, 1};
        cuuint32_t box[4]     = {PIX, CC, 1, CH_T};
        CUresult r = ((EncodeTiledFn)fn)(
            &tmap, CU_TENSOR_MAP_DATA_TYPE_FLOAT32, 4, (void*)seq,
            dims, strides, box, estr,
            CU_TENSOR_MAP_INTERLEAVE_NONE, CU_TENSOR_MAP_SWIZZLE_NONE,
            CU_TENSOR_MAP_L2_PROMOTION_L2_128B, CU_TENSOR_MAP_FLOAT_OOB_FILL_NONE);
        tma_ok = (r == CUDA_SUCCESS);
    }

    if (tma_ok) {
        cudaFuncSetAttribute(tfma_ring_kernel,
                             cudaFuncAttributeMaxDynamicSharedMemorySize, SMEM_BYTES);
        tfma_ring_kernel<<<GRID, NTHREADS, SMEM_BYTES>>>(tmap, w, bv, gamma, out);
    } else {
        cudaFuncSetAttribute(tfma_fb_kernel,
                             cudaFuncAttributeMaxDynamicSharedMemorySize, FB_SMEM_BYTES);
        tfma_fb_kernel<<<448, 512, FB_SMEM_BYTES>>>(seq, w, bv, gamma, out);
    }
}

// round 8
// speedup vs baseline: 1.0345x; 1.0345x over previous
#include <cuda_runtime.h>
#include <cuda.h>
#include <cstdint>

// ---------------- constants ----------------
#define TT    9
#define BB    8
#define CC    256
#define HWHW  3136
#define PIX   16
#define NTHREADS 1024
#define TILES_PER_B 196          // 3136/16
#define GRID  148                // persistent, 1 CTA/SM

#define A_T   3                  // t = 0..2  (double-buffered)
#define B_T   6                  // t = 3..8  (single-buffered)
#define A_FLOATS (A_T*CC*PIX)    // 12288 floats = 49152 B
#define B_FLOATS (B_T*CC*PIX)    // 24576 floats = 98304 B
#define A_BYTES  (A_FLOATS*4)
#define B_BYTES  (B_FLOATS*4)

// SMEM layout (float offsets)
#define OFF_A0   0
#define OFF_A1   (A_FLOATS)                  // 12288
#define OFF_B    (2*A_FLOATS)                // 24576
#define OFF_PART (OFF_B + B_FLOATS)          // 49152  [32 warps][160]
#define OFF_SCOR (OFF_PART + 32*160)         // 54272  [160]
#define OFF_MBAR (OFF_SCOR + 160)            // 54432  (3 x u64; byte 217728, 8B aligned)
#define SMEM_FLOATS (OFF_MBAR + 6)
#define SMEM_BYTES  (SMEM_FLOATS * 4)        // 217752 B

// ---------------- PTX helpers ----------------
#define MBAR_INIT(addr, cnt) \
    asm volatile("mbarrier.init.shared.b64 [%0], %1;" :: "r"(addr), "r"(cnt) : "memory")
#define MBAR_EXPECT_TX(addr, bytes) \
    asm volatile("mbarrier.arrive.expect_tx.shared.b64 _, [%0], %1;" :: "r"(addr), "r"(bytes) : "memory")
#define MBAR_WAIT(addr, parity) do {                                           \
    asm volatile("{\n\t.reg .pred P;\n\t"                                      \
        "WL_%=:\n\t"                                                           \
        "mbarrier.try_wait.parity.acquire.cta.shared::cta.b64 P, [%0], %1, 0x989680;\n\t" \
        "@P bra WD_%=;\n\t"                                                    \
        "bra WL_%=;\n\t"                                                       \
        "WD_%=:\n\t}"                                                          \
        :: "r"(addr), "r"(parity) : "memory");                                 \
} while (0)

__device__ __forceinline__ void tma_load4d(uint32_t dst, const CUtensorMap* map,
                                           int x, int z, int tw, uint32_t mbar)
{
    asm volatile(
        "cp.async.bulk.tensor.4d.shared::cta.global.tile.mbarrier::complete_tx::bytes "
        "[%0], [%1, {%2, %3, %4, %5}], [%6];"
        :: "r"(dst), "l"(map), "r"(x), "r"(0), "r"(z), "r"(tw), "r"(mbar)
        : "memory");
}

// ---------------- main kernel ----------------
__global__ __launch_bounds__(NTHREADS, 1)
void tfma_ab_kernel(const __grid_constant__ CUtensorMap tmapA,   // box {16,256,1,3}
                    const __grid_constant__ CUtensorMap tmapB,   // box {16,256,1,6}
                    const float* __restrict__ wptr,
                    const float* __restrict__ bptr,
                    const float* __restrict__ gptr,
                    float* __restrict__ out)
{
    extern __shared__ float sm[];
    float* part = sm + OFF_PART;
    float* scor = sm + OFF_SCOR;
    const uint32_t smem_base = (uint32_t)__cvta_generic_to_shared(sm);
    const uint32_t mbA0 = smem_base + OFF_MBAR * 4;
    const uint32_t mbA1 = mbA0 + 8;
    const uint32_t mbB  = mbA0 + 16;
    const uint32_t dstA0 = smem_base;
    const uint32_t dstA1 = smem_base + A_BYTES;
    const uint32_t dstB  = smem_base + 2 * A_BYTES;

    const int tid  = threadIdx.x;
    const int lane = tid & 31;
    const int wrp  = tid >> 5;
    const int p    = tid & (PIX - 1);   // 0..15
    const int cg   = tid >> 4;          // 0..63

    // static balanced tile range over 1568 tiles
    const int g0  = (int)(((long)blockIdx.x * 392) / 37);
    const int g1  = (int)(((long)(blockIdx.x + 1) * 392) / 37);
    const int cnt = g1 - g0;
    if (cnt <= 0) return;

    // preload weights to registers
    float wct[4], wot[4];
    #pragma unroll
    for (int ci = 0; ci < 4; ++ci) {
        wct[ci] = wptr[cg + (ci << 6)];
        wot[ci] = wptr[CC + cg + (ci << 6)];
    }
    const float bv    = bptr[0];
    const float gamma = gptr[0];

    if (tid == 0) {
        MBAR_INIT(mbA0, 1);
        MBAR_INIT(mbA1, 1);
        MBAR_INIT(mbB, 1);
    }
    __syncthreads();

    // prologue: A(g0)->A0, A(g0+1)->A1, B(g0)->B  (FIFO: A0 lands first)
    if (tid == 0) {
        {
            const int g = g0;
            MBAR_EXPECT_TX(mbA0, A_BYTES);
            tma_load4d(dstA0, &tmapA, (g % TILES_PER_B) * PIX, g / TILES_PER_B, 0, mbA0);
        }
        if (cnt > 1) {
            const int g = g0 + 1;
            MBAR_EXPECT_TX(mbA1, A_BYTES);
            tma_load4d(dstA1, &tmapA, (g % TILES_PER_B) * PIX, g / TILES_PER_B, 0, mbA1);
        }
        {
            const int g = g0;
            MBAR_EXPECT_TX(mbB, B_BYTES);
            tma_load4d(dstB, &tmapB, (g % TILES_PER_B) * PIX, g / TILES_PER_B, A_T, mbB);
        }
    }

    #pragma unroll 1
    for (int k = 0; k < cnt; ++k) {
        const int g    = g0 + k;
        const int bidx = g / TILES_PER_B;
        const int pix0 = (g % TILES_PER_B) * PIX;

        float rv[4][TT];
        float acc[TT];
        float accc = 0.f;
        #pragma unroll
        for (int t = 0; t < TT; ++t) acc[t] = 0.f;

        // ---- A chunk: t = 0..2 (slot k&1, phase (k>>1)&1) ----
        MBAR_WAIT((k & 1) ? mbA1 : mbA0, (k >> 1) & 1);
        {
            const float* buf = sm + ((k & 1) ? OFF_A1 : OFF_A0);
            #pragma unroll
            for (int ci = 0; ci < 4; ++ci) {
                const int c = cg + (ci << 6);
                #pragma unroll
                for (int t = 0; t < A_T; ++t) {
                    rv[ci][t] = buf[(t * CC + c) * PIX + p];
                    acc[t] = fmaf(rv[ci][t], wot[ci], acc[t]);
                }
            }
        }
        __syncthreads();                      // A slot consumed by all
        if (tid == 0 && k + 2 < cnt) {        // refill this A slot with tile k+2
            const int gn = g + 2;
            const uint32_t mb  = (k & 1) ? mbA1 : mbA0;
            const uint32_t dst = (k & 1) ? dstA1 : dstA0;
            MBAR_EXPECT_TX(mb, A_BYTES);
            tma_load4d(dst, &tmapA, (gn % TILES_PER_B) * PIX, gn / TILES_PER_B, 0, mb);
        }

        // ---- B chunk: t = 3..8 (phase k&1) ----
        MBAR_WAIT(mbB, k & 1);
        #pragma unroll
        for (int ci = 0; ci < 4; ++ci) {
            const int c = cg + (ci << 6);
            #pragma unroll
            for (int t = A_T; t < TT; ++t) {
                rv[ci][t] = sm[OFF_B + ((t - A_T) * CC + c) * PIX + p];
                acc[t] = fmaf(rv[ci][t], wot[ci], acc[t]);
            }
            accc = fmaf(rv[ci][TT / 2], wct[ci], accc);   // t=4 lives in B
        }
        // warp partials: xor16 combines the warp's two c-groups (same p)
        #pragma unroll
        for (int t = 0; t < TT; ++t)
            acc[t] += __shfl_xor_sync(0xffffffffu, acc[t], 16);
        accc += __shfl_xor_sync(0xffffffffu, accc, 16);
        if (lane < PIX) {
            #pragma unroll
            for (int t = 0; t < TT; ++t)
                part[wrp * 160 + t * PIX + lane] = acc[t];
            part[wrp * 160 + TT * PIX + lane] = accc;
        }
        __syncthreads();                      // B consumed + partials visible
        if (tid == 0 && k + 1 < cnt) {        // refill B with tile k+1
            const int gn = g + 1;
            MBAR_EXPECT_TX(mbB, B_BYTES);
            tma_load4d(dstB, &tmapB, (gn % TILES_PER_B) * PIX, gn / TILES_PER_B, A_T, mbB);
        }

        // ---- cross-warp reduce: 160 threads ----
        if (tid < 160) {
            float s = 0.f;
            #pragma unroll
            for (int w = 0; w < 32; ++w) s += part[w * 160 + tid];
            scor[tid] = s;
        }
        __syncthreads();

        // ---- softmax + attended sum + residual (from registers) ----
        {
            const float centv = scor[TT * PIX + p];
            float a[TT];
            float m = -1e30f;
            #pragma unroll
            for (int t = 0; t < TT; ++t) {
                a[t] = scor[t * PIX + p] + centv + bv;
                m = fmaxf(m, a[t]);
            }
            float sum = 0.f;
            #pragma unroll
            for (int t = 0; t < TT; ++t) {
                a[t] = __expf(a[t] - m);
                sum += a[t];
            }
            const float inv = 1.f / sum;
            #pragma unroll
            for (int t = 0; t < TT; ++t) a[t] *= inv;

            float* ob = out + (size_t)bidx * CC * HWHW + pix0 + p;
            #pragma unroll
            for (int ci = 0; ci < 4; ++ci) {
                const int c = cg + (ci << 6);
                float s = 0.f;
                #pragma unroll
                for (int t = 0; t < TT; ++t)
                    s = fmaf(a[t], rv[ci][t], s);
                ob[(size_t)c * HWHW] = rv[ci][TT / 2] + gamma * s;
            }
        }
        // scor/part reuse protected by next tile's barriers (see R6 analysis)
    }
}

// ---------------- fallback kernel (proven cp.async path) ----------------
#define FBPIX 8
#define FB_NT 7
#define FB_CHUNKS 56
#define FB_TILEF (TT*CC*FBPIX)
#define FB_OFF_WC   (2*FB_TILEF)
#define FB_OFF_WO   (FB_OFF_WC + CC)
#define FB_OFF_PART (FB_OFF_WO + CC)
#define FB_OFF_SCOR (FB_OFF_PART + 16*80)
#define FB_SMEM_BYTES ((FB_OFF_SCOR + 80) * 4)

__device__ __forceinline__ void fb_issue_tile(uint32_t smem_dst_bytes,
                                              const float* __restrict__ src, int tid)
{
    const int q = tid & 1;
    const int c = tid >> 1;
    const float* g = src + (size_t)c * HWHW + q * 4;
    uint32_t s = smem_dst_bytes + (uint32_t)((c * FBPIX + q * 4) * 4);
    #pragma unroll
    for (int t = 0; t < TT; ++t) {
        asm volatile("cp.async.cg.shared.global [%0], [%1], 16;\n"
                     :: "r"(s), "l"(g) : "memory");
        g += (size_t)BB * CC * HWHW;
        s += CC * FBPIX * 4;
    }
}

__global__ __launch_bounds__(512, 1)
void tfma_fb_kernel(const float* __restrict__ seq,
                    const float* __restrict__ wptr,
                    const float* __restrict__ bptr,
                    const float* __restrict__ gptr,
                    float* __restrict__ out)
{
    extern __shared__ float sm[];
    float* wc   = sm + FB_OFF_WC;
    float* wo   = sm + FB_OFF_WO;
    float* part = sm + FB_OFF_PART;
    float* scor = sm + FB_OFF_SCOR;
    const uint32_t smem_base = (uint32_t)__cvta_generic_to_shared(sm);

    const int tid  = threadIdx.x;
    const int lane = tid & 31;
    const int wrp  = tid >> 5;
    const int p    = tid & (FBPIX - 1);
    const int cg   = tid >> 3;
    const int bidx  = blockIdx.x / FB_CHUNKS;
    const int chunk = blockIdx.x % FB_CHUNKS;
    const float* tbase = seq + (size_t)bidx * CC * HWHW;

    if (tid < CC) { wc[tid] = wptr[tid]; wo[tid] = wptr[CC + tid]; }

    fb_issue_tile(smem_base, tbase + (size_t)(chunk * FB_NT) * FBPIX, tid);
    asm volatile("cp.async.commit_group;\n" ::: "memory");

    const float bv    = bptr[0];
    const float gamma = gptr[0];
    float* obase0 = out + (size_t)bidx * CC * HWHW;

    for (int k = 0; k < FB_NT; ++k) {
        if (k + 1 < FB_NT)
            fb_issue_tile(smem_base + ((k & 1) ? 0 : FB_TILEF) * 4,
                          tbase + (size_t)((chunk * FB_NT + k + 1) * FBPIX), tid);
        asm volatile("cp.async.commit_group;\n" ::: "memory");
        asm volatile("cp.async.wait_group 1;\n" ::: "memory");
        __syncthreads();

        const float* tile = sm + ((k & 1) ? FB_TILEF : 0);
        const int pix0 = (chunk * FB_NT + k) * FBPIX;

        float rv[4][TT];
        float acc[TT]; float accc = 0.f;
        #pragma unroll
        for (int t = 0; t < TT; ++t) acc[t] = 0.f;
        #pragma unroll
        for (int ci = 0; ci < 4; ++ci) {
            const int c = cg + (ci << 6);
            const float wotv = wo[c], wctv = wc[c];
            #pragma unroll
            for (int t = 0; t < TT; ++t) {
                rv[ci][t] = tile[(t * CC + c) * FBPIX + p];
                acc[t] = fmaf(rv[ci][t], wotv, acc[t]);
                if (t == TT / 2) accc = fmaf(rv[ci][t], wctv, accc);
            }
        }
        #pragma unroll
        for (int t = 0; t < TT; ++t) {
            acc[t] += __shfl_xor_sync(0xffffffffu, acc[t], 8);
            acc[t] += __shfl_xor_sync(0xffffffffu, acc[t], 16);
        }
        accc += __shfl_xor_sync(0xffffffffu, accc, 8);
        accc += __shfl_xor_sync(0xffffffffu, accc, 16);
        if (lane < FBPIX) {
            #pragma unroll
            for (int t = 0; t < TT; ++t) part[wrp * 80 + t * FBPIX + lane] = acc[t];
            part[wrp * 80 + TT * FBPIX + lane] = accc;
        }
        __syncthreads();
        if (tid < 80) {
            float s = 0.f;
            #pragma unroll
            for (int g = 0; g < 16; ++g) s += part[g * 80 + tid];
            scor[tid] = s;
        }
        __syncthreads();
        {
            const float centv = scor[TT * FBPIX + p];
            float a[TT]; float m = -1e30f;
            #pragma unroll
            for (int t = 0; t < TT; ++t) { a[t] = scor[t * FBPIX + p] + centv + bv; m = fmaxf(m, a[t]); }
            float sum = 0.f;
            #pragma unroll
            for (int t = 0; t < TT; ++t) { a[t] = __expf(a[t] - m); sum += a[t]; }
            const float inv = 1.f / sum;
            #pragma unroll
            for (int t = 0; t < TT; ++t) a[t] *= inv;

            float* ob = obase0 + pix0 + p;
            #pragma unroll
            for (int ci = 0; ci < 4; ++ci) {
                const int c = cg + (ci << 6);
                float s = 0.f;
                #pragma unroll
                for (int t = 0; t < TT; ++t) s = fmaf(a[t], rv[ci][t], s);
                ob[(size_t)c * HWHW] = rv[ci][TT / 2] + gamma * s;
            }
        }
        __syncthreads();
    }
}

// ---------------- host ----------------
typedef CUresult (*EncodeTiledFn)(CUtensorMap*, CUtensorMapDataType, cuuint32_t, void*,
                                  const cuuint64_t*, const cuuint64_t*,
                                  const cuuint32_t*, const cuuint32_t*,
                                  CUtensorMapInterleave, CUtensorMapSwizzle,
                                  CUtensorMapL2promotion, CUtensorMapFloatOOBfill);

extern "C" void kernel_launch(void* const* d_in, const int* in_sizes, int n_in,
                              void* d_out, int out_size)
{
    (void)in_sizes; (void)n_in; (void)out_size;
    const float* seq   = (const float*)d_in[0];
    const float* w     = (const float*)d_in[1];
    const float* bv    = (const float*)d_in[2];
    const float* gamma = (const float*)d_in[3];
    float* out = (float*)d_out;

    void* fn = nullptr;
    cudaDriverEntryPointQueryResult qr = cudaDriverEntryPointSymbolNotFound;
    cudaGetDriverEntryPointByVersion("cuTensorMapEncodeTiled", &fn, 12000,
                                     cudaEnableDefault, &qr);

    bool tma_ok = false;
    CUtensorMap tmapA, tmapB;
    if (fn && qr == cudaDriverEntryPointSuccess) {
        cuuint64_t dims[4]    = {HWHW, CC, BB, TT};
        cuuint64_t strides[3] = {(cuuint64_t)HWHW * 4,
                                 (cuuint64_t)CC * HWHW * 4,
                                 (cuuint64_t)BB * CC * HWHW * 4};
        cuuint32_t estr[4]    = {1, 1, 1, 1};
        cuuint32_t boxA[4]    = {PIX, CC, 1, A_T};
        cuuint32_t boxB[4]    = {PIX, CC, 1, B_T};
        CUresult rA = ((EncodeTiledFn)fn)(
            &tmapA, CU_TENSOR_MAP_DATA_TYPE_FLOAT32, 4, (void*)seq,
            dims, strides, boxA, estr,
            CU_TENSOR_MAP_INTERLEAVE_NONE, CU_TENSOR_MAP_SWIZZLE_NONE,
            CU_TENSOR_MAP_L2_PROMOTION_L2_128B, CU_TENSOR_MAP_FLOAT_OOB_FILL_NONE);
        CUresult rB = ((EncodeTiledFn)fn)(
            &tmapB, CU_TENSOR_MAP_DATA_TYPE_FLOAT32, 4, (void*)seq,
            dims, strides, boxB, estr,
            CU_TENSOR_MAP_INTERLEAVE_NONE, CU_TENSOR_MAP_SWIZZLE_NONE,
            CU_TENSOR_MAP_L2_PROMOTION_L2_128B, CU_TENSOR_MAP_FLOAT_OOB_FILL_NONE);
        tma_ok = (rA == CUDA_SUCCESS && rB == CUDA_SUCCESS);
    }

    if (tma_ok) {
        cudaFuncSetAttribute(tfma_ab_kernel,
                             cudaFuncAttributeMaxDynamicSharedMemorySize, SMEM_BYTES);
        tfma_ab_kernel<<<GRID, NTHREADS, SMEM_BYTES>>>(tmapA, tmapB, w, bv, gamma, out);
    } else {
        cudaFuncSetAttribute(tfma_fb_kernel,
                             cudaFuncAttributeMaxDynamicSharedMemorySize, FB_SMEM_BYTES);
        tfma_fb_kernel<<<448, 512, FB_SMEM_BYTES>>>(seq, w, bv, gamma, out);
    }
}